// round 1
// baseline (speedup 1.0000x reference)
#include <cuda_runtime.h>
#include <cstdint>

#define NN 50000
#define KD 128

// ---------------- scratch (device globals; no allocation allowed) ----------
__device__ float g_deg_src[NN];
__device__ float g_deg_dst[NN];
__device__ float g_norm_src[NN];
__device__ float g_norm_dst[NN];
__device__ float g_y[(size_t)NN * 128];
__device__ float g_agg[(size_t)NN * 128];
__device__ float g_h[(size_t)NN * 128];

// ---------------- tiny kernels --------------------------------------------
__global__ void zero_kernel(float4* __restrict__ p, int n4) {
    int i = blockIdx.x * blockDim.x + threadIdx.x;
    if (i < n4) p[i] = make_float4(0.f, 0.f, 0.f, 0.f);
}

__global__ void deg_kernel(const int* __restrict__ src, const int* __restrict__ dst, int E) {
    int i = blockIdx.x * blockDim.x + threadIdx.x;
    if (i < E) {
        atomicAdd(&g_deg_src[src[i]], 1.0f);
        atomicAdd(&g_deg_dst[dst[i]], 1.0f);
    }
}

__global__ void norm_kernel() {
    int i = blockIdx.x * blockDim.x + threadIdx.x;
    if (i < NN) {
        g_norm_src[i] = rsqrtf(fmaxf(g_deg_src[i], 1.0f));
        g_norm_dst[i] = rsqrtf(fmaxf(g_deg_dst[i], 1.0f));
    }
}

// ---------------- GEMM: Y[i,:] = scale[i] * (X[i,:] @ W), K=128 fixed ------
// BM=64 rows per block, 256 threads, BK=32. Thread tile TM x TN.
template <int D>
__global__ void __launch_bounds__(256)
gemm_scale_kernel(const float* __restrict__ X, const float* __restrict__ W,
                  const float* __restrict__ scale, float* __restrict__ Y, int n) {
    constexpr int BM = 64;
    constexpr int BK = 32;
    constexpr int TM = 4;
    constexpr int TN = (BM * D) / (256 * TM);  // D=128 -> 8, D=64 -> 4

    __shared__ float Xs[BM][BK + 4];
    __shared__ float Ws[BK][D];

    const int tid  = threadIdx.x;
    const int row0 = blockIdx.x * BM;
    const int tr   = tid / 16;   // 0..15  (row group)
    const int tc   = tid % 16;   // 0..15  (col group)

    float acc[TM][TN];
#pragma unroll
    for (int m = 0; m < TM; m++)
#pragma unroll
        for (int j = 0; j < TN; j++) acc[m][j] = 0.f;

    for (int k0 = 0; k0 < KD; k0 += BK) {
        // load X tile: 64x32 floats = 512 float4, 2 per thread
#pragma unroll
        for (int i = 0; i < 2; i++) {
            int lin = tid + i * 256;
            int r  = lin >> 3;        // /8
            int kq = lin & 7;         // %8
            float4 v = make_float4(0.f, 0.f, 0.f, 0.f);
            int gr = row0 + r;
            if (gr < n)
                v = *(const float4*)(X + (size_t)gr * KD + k0 + kq * 4);
            Xs[r][kq * 4 + 0] = v.x;
            Xs[r][kq * 4 + 1] = v.y;
            Xs[r][kq * 4 + 2] = v.z;
            Xs[r][kq * 4 + 3] = v.w;
        }
        // load W tile: BK x D floats
        constexpr int WL = (BK * D) / (4 * 256);  // D=128 -> 4, D=64 -> 2
#pragma unroll
        for (int i = 0; i < WL; i++) {
            int lin = tid + i * 256;
            int k  = lin / (D / 4);
            int cq = lin % (D / 4);
            *(float4*)&Ws[k][cq * 4] = *(const float4*)(W + (size_t)(k0 + k) * D + cq * 4);
        }
        __syncthreads();

#pragma unroll
        for (int kk = 0; kk < BK; kk++) {
            float a[TM], b[TN];
#pragma unroll
            for (int m = 0; m < TM; m++) a[m] = Xs[tr * TM + m][kk];
#pragma unroll
            for (int j = 0; j < TN; j++) b[j] = Ws[kk][tc * TN + j];
#pragma unroll
            for (int m = 0; m < TM; m++)
#pragma unroll
                for (int j = 0; j < TN; j++) acc[m][j] += a[m] * b[j];
        }
        __syncthreads();
    }

    // epilogue: apply per-row scale (norm_src), write Y
#pragma unroll
    for (int m = 0; m < TM; m++) {
        int r = row0 + tr * TM + m;
        if (r < n) {
            float sc = scale[r];
#pragma unroll
            for (int j = 0; j < TN; j++)
                Y[(size_t)r * D + tc * TN + j] = acc[m][j] * sc;
        }
    }
}

// ---------------- edge scatter: agg[dst] += y[src], vectorized atomics -----
__device__ __forceinline__ void red_add_f4(float* p, float4 v) {
    asm volatile("red.global.add.v4.f32 [%0], {%1, %2, %3, %4};"
                 :: "l"(p), "f"(v.x), "f"(v.y), "f"(v.z), "f"(v.w)
                 : "memory");
}

template <int D>
__global__ void scatter_kernel(const float* __restrict__ Y, const int* __restrict__ src,
                               const int* __restrict__ dst, float* __restrict__ agg, int E) {
    constexpr int LPE = D / 4;  // float4 lanes per edge (32 or 16)
    int idx = blockIdx.x * blockDim.x + threadIdx.x;
    int e = idx / LPE;
    int c = idx % LPE;
    if (e >= E) return;
    int s = src[e];
    int d = dst[e];
    float4 v = *(const float4*)(Y + (size_t)s * D + c * 4);
    red_add_f4(agg + (size_t)d * D + c * 4, v);
}

// ---------------- epilogue: out = [relu](agg * norm_dst + b) ---------------
template <int D, bool RELU>
__global__ void epilogue_kernel(const float* __restrict__ agg, const float* __restrict__ nd,
                                const float* __restrict__ bias, float* __restrict__ out, int n) {
    constexpr int CQ = D / 4;
    int idx = blockIdx.x * blockDim.x + threadIdx.x;
    if (idx >= n * CQ) return;
    int r  = idx / CQ;
    int cq = idx % CQ;
    float4 v  = *(const float4*)(agg + (size_t)r * D + cq * 4);
    float4 bb = *(const float4*)(bias + cq * 4);
    float  s  = nd[r];
    v.x = v.x * s + bb.x;
    v.y = v.y * s + bb.y;
    v.z = v.z * s + bb.z;
    v.w = v.w * s + bb.w;
    if (RELU) {
        v.x = fmaxf(v.x, 0.f);
        v.y = fmaxf(v.y, 0.f);
        v.z = fmaxf(v.z, 0.f);
        v.w = fmaxf(v.w, 0.f);
    }
    *(float4*)(out + (size_t)r * D + cq * 4) = v;
}

// ---------------- host orchestration ---------------------------------------
extern "C" void kernel_launch(void* const* d_in, const int* in_sizes, int n_in,
                              void* d_out, int out_size) {
    const float* features = (const float*)d_in[0];
    const float* W1 = (const float*)d_in[1];
    const float* b1 = (const float*)d_in[2];
    const float* W2 = (const float*)d_in[3];
    const float* b2 = (const float*)d_in[4];
    const float* W3 = (const float*)d_in[5];
    const float* b3 = (const float*)d_in[6];
    const int*   src = (const int*)d_in[7];
    const int*   dst = (const int*)d_in[8];
    const int E = in_sizes[7];
    const int n = NN;
    float* out = (float*)d_out;

    // symbol addresses (host-side, capture-safe: immediate, no stream ops)
    float *deg_s, *deg_d, *nrm_s, *nrm_d, *y, *agg, *h;
    cudaGetSymbolAddress((void**)&deg_s, g_deg_src);
    cudaGetSymbolAddress((void**)&deg_d, g_deg_dst);
    cudaGetSymbolAddress((void**)&nrm_s, g_norm_src);
    cudaGetSymbolAddress((void**)&nrm_d, g_norm_dst);
    cudaGetSymbolAddress((void**)&y,   g_y);
    cudaGetSymbolAddress((void**)&agg, g_agg);
    cudaGetSymbolAddress((void**)&h,   g_h);

    const int TPB = 256;
    // --- degrees + norms ---
    zero_kernel<<<(NN / 4 + TPB - 1) / TPB, TPB>>>((float4*)deg_s, NN / 4);
    zero_kernel<<<(NN / 4 + TPB - 1) / TPB, TPB>>>((float4*)deg_d, NN / 4);
    deg_kernel<<<(E + TPB - 1) / TPB, TPB>>>(src, dst, E);
    norm_kernel<<<(NN + TPB - 1) / TPB, TPB>>>();

    const int gemm_blocks = (n + 63) / 64;
    const int agg4_128 = n * 32;  // NN*128/4 float4
    const int agg4_64  = n * 16;

    // --- layer 1: 128 -> 128, relu ---
    gemm_scale_kernel<128><<<gemm_blocks, 256>>>(features, W1, nrm_s, y, n);
    zero_kernel<<<(agg4_128 + TPB - 1) / TPB, TPB>>>((float4*)agg, agg4_128);
    {
        long long tot = (long long)E * 32;
        scatter_kernel<128><<<(int)((tot + TPB - 1) / TPB), TPB>>>(y, src, dst, agg, E);
    }
    epilogue_kernel<128, true><<<(n * 32 + TPB - 1) / TPB, TPB>>>(agg, nrm_d, b1, h, n);

    // --- layer 2: 128 -> 128, relu ---
    gemm_scale_kernel<128><<<gemm_blocks, 256>>>(h, W2, nrm_s, y, n);
    zero_kernel<<<(agg4_128 + TPB - 1) / TPB, TPB>>>((float4*)agg, agg4_128);
    {
        long long tot = (long long)E * 32;
        scatter_kernel<128><<<(int)((tot + TPB - 1) / TPB), TPB>>>(y, src, dst, agg, E);
    }
    epilogue_kernel<128, true><<<(n * 32 + TPB - 1) / TPB, TPB>>>(agg, nrm_d, b2, h, n);

    // --- layer 3: 128 -> 64, no relu, write d_out ---
    gemm_scale_kernel<64><<<gemm_blocks, 256>>>(h, W3, nrm_s, y, n);
    zero_kernel<<<(agg4_64 + TPB - 1) / TPB, TPB>>>((float4*)agg, agg4_64);
    {
        long long tot = (long long)E * 16;
        scatter_kernel<64><<<(int)((tot + TPB - 1) / TPB), TPB>>>(y, src, dst, agg, E);
    }
    epilogue_kernel<64, false><<<(n * 16 + TPB - 1) / TPB, TPB>>>(agg, nrm_d, b3, out, n);
}

// round 2
// speedup vs baseline: 1.5230x; 1.5230x over previous
#include <cuda_runtime.h>
#include <cstdint>

#define NN 50000
#define KD 128
#define EMAX 1000000

// ---------------- scratch (device globals; no allocation allowed) ----------
__device__ int   g_outdeg[NN];
__device__ int   g_indeg[NN];
__device__ float g_norm_src[NN];
__device__ float g_norm_dst[NN];
__device__ int   g_off[NN + 1];
__device__ int   g_cursor[NN];
__device__ int   g_chunk_sum[256];
__device__ int   g_chunk_base[256];
__device__ int   g_csrc[EMAX];
__device__ float g_y[(size_t)NN * 128];
__device__ float g_h[(size_t)NN * 128];

// ---------------- f32x2 packed-FMA helpers (Blackwell) ----------------------
__device__ __forceinline__ unsigned long long pk2(float x) {
    unsigned long long r;
    asm("mov.b64 %0, {%1, %1};" : "=l"(r) : "f"(x));
    return r;
}
__device__ __forceinline__ void fma2(unsigned long long& acc, unsigned long long a,
                                     unsigned long long b) {
    asm("fma.rn.f32x2 %0, %1, %2, %0;" : "+l"(acc) : "l"(a), "l"(b));
}
__device__ __forceinline__ float2 up2(unsigned long long v) {
    float2 f;
    asm("mov.b64 {%0, %1}, %2;" : "=f"(f.x), "=f"(f.y) : "l"(v));
    return f;
}

// ---------------- tiny kernels ----------------------------------------------
__global__ void zero_int2(int* a, int* b, int n) {
    int i = blockIdx.x * blockDim.x + threadIdx.x;
    if (i < n) { a[i] = 0; b[i] = 0; }
}

__global__ void deg_kernel(const int* __restrict__ src, const int* __restrict__ dst, int E) {
    int i = blockIdx.x * blockDim.x + threadIdx.x;
    if (i < E) {
        atomicAdd(&g_outdeg[src[i]], 1);
        atomicAdd(&g_indeg[dst[i]], 1);
    }
}

__global__ void norm_kernel() {
    int i = blockIdx.x * blockDim.x + threadIdx.x;
    if (i < NN) {
        g_norm_src[i] = rsqrtf(fmaxf((float)g_outdeg[i], 1.0f));
        g_norm_dst[i] = rsqrtf(fmaxf((float)g_indeg[i], 1.0f));
    }
}

// ---------------- exclusive scan of in-degrees (3-kernel chunked) -----------
__global__ void scan_sum_kernel() {                       // 196 blocks x 256
    __shared__ int s[256];
    int t = threadIdx.x;
    int idx = blockIdx.x * 256 + t;
    int v = (idx < NN) ? g_indeg[idx] : 0;
    s[t] = v; __syncthreads();
    for (int o = 128; o > 0; o >>= 1) {
        if (t < o) s[t] += s[t + o];
        __syncthreads();
    }
    if (t == 0) g_chunk_sum[blockIdx.x] = s[0];
}

__global__ void scan_top_kernel(int nchunk, int E) {      // 1 block x 256
    __shared__ int s[256];
    int t = threadIdx.x;
    int v = (t < nchunk) ? g_chunk_sum[t] : 0;
    s[t] = v; __syncthreads();
    for (int o = 1; o < 256; o <<= 1) {
        int x = (t >= o) ? s[t - o] : 0;
        __syncthreads();
        s[t] += x;
        __syncthreads();
    }
    if (t < nchunk) g_chunk_base[t] = s[t] - v;   // exclusive
    if (t == 0) g_off[NN] = E;
}

__global__ void scan_apply_kernel() {                     // 196 blocks x 256
    __shared__ int s[256];
    int t = threadIdx.x;
    int idx = blockIdx.x * 256 + t;
    int v = (idx < NN) ? g_indeg[idx] : 0;
    s[t] = v; __syncthreads();
    for (int o = 1; o < 256; o <<= 1) {
        int x = (t >= o) ? s[t - o] : 0;
        __syncthreads();
        s[t] += x;
        __syncthreads();
    }
    if (idx < NN) {
        int excl = g_chunk_base[blockIdx.x] + s[t] - v;
        g_off[idx] = excl;
        g_cursor[idx] = excl;
    }
}

__global__ void fill_kernel(const int* __restrict__ src, const int* __restrict__ dst, int E) {
    int e = blockIdx.x * blockDim.x + threadIdx.x;
    if (e < E) {
        int pos = atomicAdd(&g_cursor[dst[e]], 1);
        g_csrc[pos] = src[e];
    }
}

// ---------------- GEMM: Y[i,:] = ns[i] * (X[i,:] @ W), K=128, f32x2 FMA -----
template <int D>
__global__ void __launch_bounds__(256)
gemm_scale_kernel(const float* __restrict__ X, const float* __restrict__ W,
                  const float* __restrict__ scale, float* __restrict__ Y, int n) {
    constexpr int BM = 64;
    constexpr int BK = 32;
    constexpr int TM = 4;
    constexpr int TN = (BM * D) / (256 * TM);  // D=128 -> 8, D=64 -> 4
    constexpr int NP = TN / 2;                 // f32x2 pairs

    __shared__ float Xs[BM][BK + 4];
    __shared__ float Ws[BK][D];

    const int tid  = threadIdx.x;
    const int row0 = blockIdx.x * BM;
    const int tr   = tid / 16;
    const int tc   = tid % 16;

    unsigned long long acc[TM][NP];
#pragma unroll
    for (int m = 0; m < TM; m++)
#pragma unroll
        for (int p = 0; p < NP; p++) acc[m][p] = 0ull;

    for (int k0 = 0; k0 < KD; k0 += BK) {
#pragma unroll
        for (int i = 0; i < 2; i++) {
            int lin = tid + i * 256;
            int r  = lin >> 3;
            int kq = lin & 7;
            float4 v = make_float4(0.f, 0.f, 0.f, 0.f);
            int gr = row0 + r;
            if (gr < n)
                v = *(const float4*)(X + (size_t)gr * KD + k0 + kq * 4);
            Xs[r][kq * 4 + 0] = v.x;
            Xs[r][kq * 4 + 1] = v.y;
            Xs[r][kq * 4 + 2] = v.z;
            Xs[r][kq * 4 + 3] = v.w;
        }
        constexpr int WL = (BK * D) / (4 * 256);
#pragma unroll
        for (int i = 0; i < WL; i++) {
            int lin = tid + i * 256;
            int k  = lin / (D / 4);
            int cq = lin % (D / 4);
            *(float4*)&Ws[k][cq * 4] = *(const float4*)(W + (size_t)(k0 + k) * D + cq * 4);
        }
        __syncthreads();

#pragma unroll
        for (int kk = 0; kk < BK; kk++) {
            unsigned long long a2[TM], b2[NP];
#pragma unroll
            for (int m = 0; m < TM; m++) a2[m] = pk2(Xs[tr * TM + m][kk]);
#pragma unroll
            for (int p = 0; p < NP; p++)
                b2[p] = *(const unsigned long long*)&Ws[kk][tc * TN + 2 * p];
#pragma unroll
            for (int m = 0; m < TM; m++)
#pragma unroll
                for (int p = 0; p < NP; p++) fma2(acc[m][p], a2[m], b2[p]);
        }
        __syncthreads();
    }

#pragma unroll
    for (int m = 0; m < TM; m++) {
        int r = row0 + tr * TM + m;
        if (r < n) {
            float sc = scale[r];
#pragma unroll
            for (int p = 0; p < NP; p++) {
                float2 f = up2(acc[m][p]);
                f.x *= sc; f.y *= sc;
                *(float2*)(Y + (size_t)r * D + tc * TN + 2 * p) = f;
            }
        }
    }
}

// ---------------- CSR gather-aggregate + fused epilogue ---------------------
// one warp per node; lane covers D/32 floats of the row
template <bool RELU>
__global__ void __launch_bounds__(256)
gather128_kernel(const float* __restrict__ Y, const float* __restrict__ nd,
                 const float* __restrict__ bias, float* __restrict__ out) {
    int warp = (blockIdx.x * blockDim.x + threadIdx.x) >> 5;
    int lane = threadIdx.x & 31;
    if (warp >= NN) return;
    int beg = g_off[warp];
    int end = g_off[warp + 1];
    float4 acc0 = make_float4(0.f, 0.f, 0.f, 0.f);
    float4 acc1 = make_float4(0.f, 0.f, 0.f, 0.f);
    for (int base = beg; base < end; base += 32) {
        int t = base + lane;
        int sl = (t < end) ? g_csrc[t] : 0;
        int m = min(32, end - base);
        int j = 0;
        for (; j + 1 < m; j += 2) {
            int s0 = __shfl_sync(0xffffffff, sl, j);
            int s1 = __shfl_sync(0xffffffff, sl, j + 1);
            float4 v0 = *(const float4*)(Y + (size_t)s0 * 128 + lane * 4);
            float4 v1 = *(const float4*)(Y + (size_t)s1 * 128 + lane * 4);
            acc0.x += v0.x; acc0.y += v0.y; acc0.z += v0.z; acc0.w += v0.w;
            acc1.x += v1.x; acc1.y += v1.y; acc1.z += v1.z; acc1.w += v1.w;
        }
        if (j < m) {
            int s0 = __shfl_sync(0xffffffff, sl, j);
            float4 v0 = *(const float4*)(Y + (size_t)s0 * 128 + lane * 4);
            acc0.x += v0.x; acc0.y += v0.y; acc0.z += v0.z; acc0.w += v0.w;
        }
    }
    float ndv = nd[warp];
    float4 bb = *(const float4*)(bias + lane * 4);
    float4 r;
    r.x = (acc0.x + acc1.x) * ndv + bb.x;
    r.y = (acc0.y + acc1.y) * ndv + bb.y;
    r.z = (acc0.z + acc1.z) * ndv + bb.z;
    r.w = (acc0.w + acc1.w) * ndv + bb.w;
    if (RELU) {
        r.x = fmaxf(r.x, 0.f); r.y = fmaxf(r.y, 0.f);
        r.z = fmaxf(r.z, 0.f); r.w = fmaxf(r.w, 0.f);
    }
    *(float4*)(out + (size_t)warp * 128 + lane * 4) = r;
}

template <bool RELU>
__global__ void __launch_bounds__(256)
gather64_kernel(const float* __restrict__ Y, const float* __restrict__ nd,
                const float* __restrict__ bias, float* __restrict__ out) {
    int warp = (blockIdx.x * blockDim.x + threadIdx.x) >> 5;
    int lane = threadIdx.x & 31;
    if (warp >= NN) return;
    int beg = g_off[warp];
    int end = g_off[warp + 1];
    float2 acc0 = make_float2(0.f, 0.f);
    float2 acc1 = make_float2(0.f, 0.f);
    for (int base = beg; base < end; base += 32) {
        int t = base + lane;
        int sl = (t < end) ? g_csrc[t] : 0;
        int m = min(32, end - base);
        int j = 0;
        for (; j + 1 < m; j += 2) {
            int s0 = __shfl_sync(0xffffffff, sl, j);
            int s1 = __shfl_sync(0xffffffff, sl, j + 1);
            float2 v0 = *(const float2*)(Y + (size_t)s0 * 64 + lane * 2);
            float2 v1 = *(const float2*)(Y + (size_t)s1 * 64 + lane * 2);
            acc0.x += v0.x; acc0.y += v0.y;
            acc1.x += v1.x; acc1.y += v1.y;
        }
        if (j < m) {
            int s0 = __shfl_sync(0xffffffff, sl, j);
            float2 v0 = *(const float2*)(Y + (size_t)s0 * 64 + lane * 2);
            acc0.x += v0.x; acc0.y += v0.y;
        }
    }
    float ndv = nd[warp];
    float2 bb = *(const float2*)(bias + lane * 2);
    float2 r;
    r.x = (acc0.x + acc1.x) * ndv + bb.x;
    r.y = (acc0.y + acc1.y) * ndv + bb.y;
    if (RELU) { r.x = fmaxf(r.x, 0.f); r.y = fmaxf(r.y, 0.f); }
    *(float2*)(out + (size_t)warp * 64 + lane * 2) = r;
}

// ---------------- host orchestration ----------------------------------------
extern "C" void kernel_launch(void* const* d_in, const int* in_sizes, int n_in,
                              void* d_out, int out_size) {
    const float* features = (const float*)d_in[0];
    const float* W1 = (const float*)d_in[1];
    const float* b1 = (const float*)d_in[2];
    const float* W2 = (const float*)d_in[3];
    const float* b2 = (const float*)d_in[4];
    const float* W3 = (const float*)d_in[5];
    const float* b3 = (const float*)d_in[6];
    const int*   src = (const int*)d_in[7];
    const int*   dst = (const int*)d_in[8];
    const int E = in_sizes[7];
    const int n = NN;
    float* out = (float*)d_out;

    float *nrm_s, *nrm_d, *y, *h;
    int *outdeg, *indeg;
    cudaGetSymbolAddress((void**)&nrm_s,  g_norm_src);
    cudaGetSymbolAddress((void**)&nrm_d,  g_norm_dst);
    cudaGetSymbolAddress((void**)&y,      g_y);
    cudaGetSymbolAddress((void**)&h,      g_h);
    cudaGetSymbolAddress((void**)&outdeg, g_outdeg);
    cudaGetSymbolAddress((void**)&indeg,  g_indeg);

    const int TPB = 256;
    const int nchunk = (NN + 255) / 256;   // 196

    // --- degrees, norms, CSR build ---
    zero_int2<<<(NN + TPB - 1) / TPB, TPB>>>(outdeg, indeg, NN);
    deg_kernel<<<(E + TPB - 1) / TPB, TPB>>>(src, dst, E);
    norm_kernel<<<(NN + TPB - 1) / TPB, TPB>>>();
    scan_sum_kernel<<<nchunk, 256>>>();
    scan_top_kernel<<<1, 256>>>(nchunk, E);
    scan_apply_kernel<<<nchunk, 256>>>();
    fill_kernel<<<(E + TPB - 1) / TPB, TPB>>>(src, dst, E);

    const int gemm_blocks = (n + 63) / 64;
    const int gather_blocks = (n * 32 + TPB - 1) / TPB;   // warp per node

    // --- layer 1: 128 -> 128, relu ---
    gemm_scale_kernel<128><<<gemm_blocks, 256>>>(features, W1, nrm_s, y, n);
    gather128_kernel<true><<<gather_blocks, TPB>>>(y, nrm_d, b1, h);

    // --- layer 2: 128 -> 128, relu ---
    gemm_scale_kernel<128><<<gemm_blocks, 256>>>(h, W2, nrm_s, y, n);
    gather128_kernel<true><<<gather_blocks, TPB>>>(y, nrm_d, b2, h);

    // --- layer 3: 128 -> 64, no relu ---
    gemm_scale_kernel<64><<<gemm_blocks, 256>>>(h, W3, nrm_s, y, n);
    gather64_kernel<false><<<gather_blocks, TPB>>>(y, nrm_d, b3, out);
}

// round 3
// speedup vs baseline: 1.7895x; 1.1750x over previous
#include <cuda_runtime.h>
#include <cuda_bf16.h>
#include <cstdint>

#define NN 50000
#define KD 128
#define EMAX 1000000

// ---------------- scratch (device globals; no allocation allowed) ----------
__device__ int   g_outdeg[NN];
__device__ int   g_indeg[NN];
__device__ float g_norm_src[NN];
__device__ float g_norm_dst[NN];
__device__ int   g_off[NN + 1];
__device__ int   g_cursor[NN];
__device__ int   g_chunk_sum[256];
__device__ int   g_csrc[EMAX];
__device__ __nv_bfloat16 g_y[(size_t)NN * 128];
__device__ float g_h[(size_t)NN * 128];

// ---------------- f32x2 packed-FMA helpers (Blackwell) ----------------------
__device__ __forceinline__ unsigned long long pk2(float x) {
    unsigned long long r;
    asm("mov.b64 %0, {%1, %1};" : "=l"(r) : "f"(x));
    return r;
}
__device__ __forceinline__ void fma2(unsigned long long& acc, unsigned long long a,
                                     unsigned long long b) {
    asm("fma.rn.f32x2 %0, %1, %2, %0;" : "+l"(acc) : "l"(a), "l"(b));
}
__device__ __forceinline__ float2 up2(unsigned long long v) {
    float2 f;
    asm("mov.b64 {%0, %1}, %2;" : "=f"(f.x), "=f"(f.y) : "l"(v));
    return f;
}

// ---------------- tiny kernels ----------------------------------------------
__global__ void zero_int2(int* a, int* b, int n) {
    int i = blockIdx.x * blockDim.x + threadIdx.x;
    if (i < n) { a[i] = 0; b[i] = 0; }
}

__global__ void deg_kernel(const int* __restrict__ src, const int* __restrict__ dst, int E) {
    int i = blockIdx.x * blockDim.x + threadIdx.x;
    if (i < E) {
        atomicAdd(&g_outdeg[src[i]], 1);
        atomicAdd(&g_indeg[dst[i]], 1);
    }
}

// chunk sums of in-degree (196 blocks x 256)
__global__ void scan_sum_kernel() {
    __shared__ int s[256];
    int t = threadIdx.x;
    int idx = blockIdx.x * 256 + t;
    int v = (idx < NN) ? g_indeg[idx] : 0;
    s[t] = v; __syncthreads();
    for (int o = 128; o > 0; o >>= 1) {
        if (t < o) s[t] += s[t + o];
        __syncthreads();
    }
    if (t == 0) g_chunk_sum[blockIdx.x] = s[0];
}

// per-block: redundant top-scan of chunk sums + local scan + norms
__global__ void scan_apply_kernel(int nchunk, int E) {
    __shared__ int cs[256];
    __shared__ int s[256];
    int t = threadIdx.x;
    int cv = (t < nchunk) ? g_chunk_sum[t] : 0;
    cs[t] = cv; __syncthreads();
    for (int o = 1; o < 256; o <<= 1) {
        int x = (t >= o) ? cs[t - o] : 0;
        __syncthreads();
        cs[t] += x;
        __syncthreads();
    }
    int base = (blockIdx.x == 0) ? 0 : cs[blockIdx.x - 1];

    int idx = blockIdx.x * 256 + t;
    int v = (idx < NN) ? g_indeg[idx] : 0;
    s[t] = v; __syncthreads();
    for (int o = 1; o < 256; o <<= 1) {
        int x = (t >= o) ? s[t - o] : 0;
        __syncthreads();
        s[t] += x;
        __syncthreads();
    }
    if (idx < NN) {
        int excl = base + s[t] - v;
        g_off[idx] = excl;
        g_cursor[idx] = excl;
        g_norm_src[idx] = rsqrtf(fmaxf((float)g_outdeg[idx], 1.0f));
        g_norm_dst[idx] = rsqrtf(fmaxf((float)v, 1.0f));
    }
    if (idx == 0) g_off[NN] = E;
}

__global__ void fill_kernel(const int* __restrict__ src, const int* __restrict__ dst, int E) {
    int e = blockIdx.x * blockDim.x + threadIdx.x;
    if (e < E) {
        int pos = atomicAdd(&g_cursor[dst[e]], 1);
        g_csrc[pos] = src[e];
    }
}

// ---------------- GEMM: Y[i,:] = [ns[i]] * (X[i,:] @ W)  -> bf16 Y ----------
template <int D, bool SCALE>
__global__ void __launch_bounds__(256)
gemm_kernel(const float* __restrict__ X, const float* __restrict__ W,
            const float* __restrict__ scale, __nv_bfloat16* __restrict__ Y, int n) {
    constexpr int BM = 64;
    constexpr int BK = 32;
    constexpr int TM = 4;
    constexpr int TN = (BM * D) / (256 * TM);  // 8 (D=128) / 4 (D=64)
    constexpr int NP = TN / 2;

    __shared__ float Xs[BM][BK + 4];
    __shared__ float Ws[BK][D];

    const int tid  = threadIdx.x;
    const int row0 = blockIdx.x * BM;
    const int tr   = tid / 16;
    const int tc   = tid % 16;

    unsigned long long acc[TM][NP];
#pragma unroll
    for (int m = 0; m < TM; m++)
#pragma unroll
        for (int p = 0; p < NP; p++) acc[m][p] = 0ull;

    for (int k0 = 0; k0 < KD; k0 += BK) {
#pragma unroll
        for (int i = 0; i < 2; i++) {
            int lin = tid + i * 256;
            int r  = lin >> 3;
            int kq = lin & 7;
            float4 v = make_float4(0.f, 0.f, 0.f, 0.f);
            int gr = row0 + r;
            if (gr < n)
                v = *(const float4*)(X + (size_t)gr * KD + k0 + kq * 4);
            Xs[r][kq * 4 + 0] = v.x;
            Xs[r][kq * 4 + 1] = v.y;
            Xs[r][kq * 4 + 2] = v.z;
            Xs[r][kq * 4 + 3] = v.w;
        }
        constexpr int WL = (BK * D) / (4 * 256);
#pragma unroll
        for (int i = 0; i < WL; i++) {
            int lin = tid + i * 256;
            int k  = lin / (D / 4);
            int cq = lin % (D / 4);
            *(float4*)&Ws[k][cq * 4] = *(const float4*)(W + (size_t)(k0 + k) * D + cq * 4);
        }
        __syncthreads();

#pragma unroll
        for (int kk = 0; kk < BK; kk++) {
            unsigned long long a2[TM], b2[NP];
#pragma unroll
            for (int m = 0; m < TM; m++) a2[m] = pk2(Xs[tr * TM + m][kk]);
#pragma unroll
            for (int p = 0; p < NP; p++)
                b2[p] = *(const unsigned long long*)&Ws[kk][tc * TN + 2 * p];
#pragma unroll
            for (int m = 0; m < TM; m++)
#pragma unroll
                for (int p = 0; p < NP; p++) fma2(acc[m][p], a2[m], b2[p]);
        }
        __syncthreads();
    }

#pragma unroll
    for (int m = 0; m < TM; m++) {
        int r = row0 + tr * TM + m;
        if (r < n) {
            float sc = SCALE ? scale[r] : 1.0f;
#pragma unroll
            for (int p = 0; p < NP; p++) {
                float2 f = up2(acc[m][p]);
                if (SCALE) { f.x *= sc; f.y *= sc; }
                __nv_bfloat162 b = __float22bfloat162_rn(f);
                *(__nv_bfloat162*)(Y + (size_t)r * D + tc * TN + 2 * p) = b;
            }
        }
    }
}

// ---------------- CSR gather-aggregate (bf16 in, fp32 accum) ----------------
template <bool RELU, bool SRCNORM>
__global__ void __launch_bounds__(256)
gather128_kernel(const __nv_bfloat16* __restrict__ Y, const float* __restrict__ ns,
                 const float* __restrict__ nd, const float* __restrict__ bias,
                 float* __restrict__ out) {
    int warp = (blockIdx.x * blockDim.x + threadIdx.x) >> 5;
    int lane = threadIdx.x & 31;
    if (warp >= NN) return;
    int beg = g_off[warp];
    int end = g_off[warp + 1];
    float4 acc0 = make_float4(0.f, 0.f, 0.f, 0.f);
    float4 acc1 = make_float4(0.f, 0.f, 0.f, 0.f);
    for (int base = beg; base < end; base += 32) {
        int t = base + lane;
        int sl = (t < end) ? g_csrc[t] : 0;
        int m = min(32, end - base);
        int j = 0;
        for (; j + 1 < m; j += 2) {
            int s0 = __shfl_sync(0xffffffff, sl, j);
            int s1 = __shfl_sync(0xffffffff, sl, j + 1);
            uint2 u0 = *(const uint2*)(Y + (size_t)s0 * 128 + lane * 4);
            uint2 u1 = *(const uint2*)(Y + (size_t)s1 * 128 + lane * 4);
            float2 a0 = __bfloat1622float2(*(const __nv_bfloat162*)&u0.x);
            float2 a1 = __bfloat1622float2(*(const __nv_bfloat162*)&u0.y);
            float2 c0 = __bfloat1622float2(*(const __nv_bfloat162*)&u1.x);
            float2 c1 = __bfloat1622float2(*(const __nv_bfloat162*)&u1.y);
            if (SRCNORM) {
                float w0 = __ldg(&ns[s0]);
                float w1 = __ldg(&ns[s1]);
                acc0.x += a0.x * w0; acc0.y += a0.y * w0;
                acc0.z += a1.x * w0; acc0.w += a1.y * w0;
                acc1.x += c0.x * w1; acc1.y += c0.y * w1;
                acc1.z += c1.x * w1; acc1.w += c1.y * w1;
            } else {
                acc0.x += a0.x; acc0.y += a0.y; acc0.z += a1.x; acc0.w += a1.y;
                acc1.x += c0.x; acc1.y += c0.y; acc1.z += c1.x; acc1.w += c1.y;
            }
        }
        if (j < m) {
            int s0 = __shfl_sync(0xffffffff, sl, j);
            uint2 u0 = *(const uint2*)(Y + (size_t)s0 * 128 + lane * 4);
            float2 a0 = __bfloat1622float2(*(const __nv_bfloat162*)&u0.x);
            float2 a1 = __bfloat1622float2(*(const __nv_bfloat162*)&u0.y);
            float w0 = SRCNORM ? __ldg(&ns[s0]) : 1.0f;
            acc0.x += a0.x * w0; acc0.y += a0.y * w0;
            acc0.z += a1.x * w0; acc0.w += a1.y * w0;
        }
    }
    float ndv = nd[warp];
    float4 bb = *(const float4*)(bias + lane * 4);
    float4 r;
    r.x = (acc0.x + acc1.x) * ndv + bb.x;
    r.y = (acc0.y + acc1.y) * ndv + bb.y;
    r.z = (acc0.z + acc1.z) * ndv + bb.z;
    r.w = (acc0.w + acc1.w) * ndv + bb.w;
    if (RELU) {
        r.x = fmaxf(r.x, 0.f); r.y = fmaxf(r.y, 0.f);
        r.z = fmaxf(r.z, 0.f); r.w = fmaxf(r.w, 0.f);
    }
    *(float4*)(out + (size_t)warp * 128 + lane * 4) = r;
}

template <bool RELU>
__global__ void __launch_bounds__(256)
gather64_kernel(const __nv_bfloat16* __restrict__ Y, const float* __restrict__ nd,
                const float* __restrict__ bias, float* __restrict__ out) {
    int warp = (blockIdx.x * blockDim.x + threadIdx.x) >> 5;
    int lane = threadIdx.x & 31;
    if (warp >= NN) return;
    int beg = g_off[warp];
    int end = g_off[warp + 1];
    float2 acc0 = make_float2(0.f, 0.f);
    float2 acc1 = make_float2(0.f, 0.f);
    for (int base = beg; base < end; base += 32) {
        int t = base + lane;
        int sl = (t < end) ? g_csrc[t] : 0;
        int m = min(32, end - base);
        int j = 0;
        for (; j + 1 < m; j += 2) {
            int s0 = __shfl_sync(0xffffffff, sl, j);
            int s1 = __shfl_sync(0xffffffff, sl, j + 1);
            unsigned u0 = *(const unsigned*)(Y + (size_t)s0 * 64 + lane * 2);
            unsigned u1 = *(const unsigned*)(Y + (size_t)s1 * 64 + lane * 2);
            float2 a0 = __bfloat1622float2(*(const __nv_bfloat162*)&u0);
            float2 a1 = __bfloat1622float2(*(const __nv_bfloat162*)&u1);
            acc0.x += a0.x; acc0.y += a0.y;
            acc1.x += a1.x; acc1.y += a1.y;
        }
        if (j < m) {
            int s0 = __shfl_sync(0xffffffff, sl, j);
            unsigned u0 = *(const unsigned*)(Y + (size_t)s0 * 64 + lane * 2);
            float2 a0 = __bfloat1622float2(*(const __nv_bfloat162*)&u0);
            acc0.x += a0.x; acc0.y += a0.y;
        }
    }
    float ndv = nd[warp];
    float2 bb = *(const float2*)(bias + lane * 2);
    float2 r;
    r.x = (acc0.x + acc1.x) * ndv + bb.x;
    r.y = (acc0.y + acc1.y) * ndv + bb.y;
    if (!RELU) {
        // no-op; template kept for symmetry
    } else {
        r.x = fmaxf(r.x, 0.f); r.y = fmaxf(r.y, 0.f);
    }
    *(float2*)(out + (size_t)warp * 64 + lane * 2) = r;
}

// ---------------- host orchestration ----------------------------------------
extern "C" void kernel_launch(void* const* d_in, const int* in_sizes, int n_in,
                              void* d_out, int out_size) {
    const float* features = (const float*)d_in[0];
    const float* W1 = (const float*)d_in[1];
    const float* b1 = (const float*)d_in[2];
    const float* W2 = (const float*)d_in[3];
    const float* b2 = (const float*)d_in[4];
    const float* W3 = (const float*)d_in[5];
    const float* b3 = (const float*)d_in[6];
    const int*   src = (const int*)d_in[7];
    const int*   dst = (const int*)d_in[8];
    const int E = in_sizes[7];
    const int n = NN;
    float* out = (float*)d_out;

    float *nrm_s, *nrm_d, *h;
    __nv_bfloat16* y;
    int *outdeg, *indeg;
    cudaGetSymbolAddress((void**)&nrm_s,  g_norm_src);
    cudaGetSymbolAddress((void**)&nrm_d,  g_norm_dst);
    cudaGetSymbolAddress((void**)&y,      g_y);
    cudaGetSymbolAddress((void**)&h,      g_h);
    cudaGetSymbolAddress((void**)&outdeg, g_outdeg);
    cudaGetSymbolAddress((void**)&indeg,  g_indeg);

    // persistent side stream + events for fork-join inside graph capture
    static cudaStream_t s2 = nullptr;
    static cudaEvent_t evFork = nullptr, evJoin = nullptr;
    if (s2 == nullptr) {
        cudaStreamCreateWithFlags(&s2, cudaStreamNonBlocking);
        cudaEventCreateWithFlags(&evFork, cudaEventDisableTiming);
        cudaEventCreateWithFlags(&evJoin, cudaEventDisableTiming);
    }

    const int TPB = 256;
    const int nchunk = (NN + 255) / 256;   // 196
    const int gemm_blocks = (n + 63) / 64;
    const int gather_blocks = (n * 32 + TPB - 1) / TPB;

    // fork: GEMM-1 (depends only on inputs) runs concurrently with CSR build
    cudaEventRecord(evFork, 0);
    cudaStreamWaitEvent(s2, evFork, 0);
    gemm_kernel<128, false><<<gemm_blocks, 256, 0, s2>>>(features, W1, nullptr, y, n);
    cudaEventRecord(evJoin, s2);

    // setup chain on main stream
    zero_int2<<<(NN + TPB - 1) / TPB, TPB>>>(outdeg, indeg, NN);
    deg_kernel<<<(E + TPB - 1) / TPB, TPB>>>(src, dst, E);
    scan_sum_kernel<<<nchunk, 256>>>();
    scan_apply_kernel<<<nchunk, 256>>>(nchunk, E);
    fill_kernel<<<(E + TPB - 1) / TPB, TPB>>>(src, dst, E);

    // join
    cudaStreamWaitEvent(0, evJoin, 0);

    // --- layer 1: gather applies norm_src per-edge (GEMM-1 ran unscaled) ---
    gather128_kernel<true, true><<<gather_blocks, TPB>>>(y, nrm_s, nrm_d, b1, h);

    // --- layer 2 ---
    gemm_kernel<128, true><<<gemm_blocks, 256>>>(h, W2, nrm_s, y, n);
    gather128_kernel<true, false><<<gather_blocks, TPB>>>(y, nullptr, nrm_d, b2, h);

    // --- layer 3 ---
    gemm_kernel<64, true><<<gemm_blocks, 256>>>(h, W3, nrm_s, y, n);
    gather64_kernel<false><<<gather_blocks, TPB>>>(y, nrm_d, b3, out);
}